// round 2
// baseline (speedup 1.0000x reference)
#include <cuda_runtime.h>
#include <cuda_bf16.h>
#include <cstdint>

// ---------------------------------------------------------------------------
// PPEG: out = dwconv7(x) + x + dwconv5(x) + dwconv3(x)  (depthwise, per-channel)
// Folded into ONE 7x7x7 depthwise conv per channel + combined bias.
// Compute uses packed fma.rn.f32x2 over the 16 d-outputs (2 per FFMA2).
//
// x layout  (per channel c): volume[d][h][w], d=16, h=64, w=64 (w contiguous)
// out layout(per channel c): [h][w][d] with d contiguous (stride-1)
// ---------------------------------------------------------------------------

#define NCH   512
#define DD    16
#define HH    64
#define WW    64
#define VOL   (DD*HH*WW)      // 65536 per channel

#define WSTRIDE 352           // per-channel slot in g_wcomb (343 taps + bias)
__device__ float g_wcomb[NCH * WSTRIDE];

typedef unsigned long long u64;
typedef unsigned int u32;

#define FMA2(d_, a_, b_, c_) \
    asm("fma.rn.f32x2 %0, %1, %2, %3;" : "=l"(d_) : "l"(a_), "l"(b_), "l"(c_))
#define PACK2(out_, lo_, hi_) \
    asm("mov.b64 %0, {%1, %2};" : "=l"(out_) : "r"(lo_), "r"(hi_))
#define UNPACK2(lo_, hi_, in_) \
    asm("mov.b64 {%0, %1}, %2;" : "=r"(lo_), "=r"(hi_) : "l"(in_))

// -------------------- weight folding --------------------
__global__ void fold_weights_kernel(const float* __restrict__ w7,
                                    const float* __restrict__ b7,
                                    const float* __restrict__ w5,
                                    const float* __restrict__ b5,
                                    const float* __restrict__ w3,
                                    const float* __restrict__ b3) {
    int c = blockIdx.x;
    for (int t = threadIdx.x; t < 343; t += blockDim.x) {
        int dd = t / 49;
        int r  = t % 49;
        int dh = r / 7;
        int dw = r % 7;
        float v = w7[c * 343 + t];
        if (dd >= 1 && dd <= 5 && dh >= 1 && dh <= 5 && dw >= 1 && dw <= 5)
            v += w5[c * 125 + (dd - 1) * 25 + (dh - 1) * 5 + (dw - 1)];
        if (dd >= 2 && dd <= 4 && dh >= 2 && dh <= 4 && dw >= 2 && dw <= 4)
            v += w3[c * 27 + (dd - 2) * 9 + (dh - 2) * 3 + (dw - 2)];
        if (t == 171) v += 1.0f;   // identity: center tap (3,3,3)
        g_wcomb[c * WSTRIDE + t] = v;
    }
    if (threadIdx.x == 0)
        g_wcomb[c * WSTRIDE + 343] = b7[c] + b5[c] + b3[c];
}

// -------------------- main conv --------------------
// CTA: one channel, 4 consecutive h rows, full W, full D.
// Thread: one (h,w) -> 16 d-outputs (8 packed f32x2 accumulators).
// Smem tile TRANSPOSED to d-innermost: [sh=10][sw=70][sd_pad=26]
#define SM_D  22
#define SDP   26              // padded d stride (even for LDS.64 align, conflict-free)
#define SM_H  10
#define SM_W  70
#define TILE_FLOATS (SM_H * SM_W * SDP)      // 18200
#define SMEM_BYTES  (TILE_FLOATS * 4 + 343 * 8)

__global__ __launch_bounds__(256)
void ppeg_conv_kernel(const float* __restrict__ x, float* __restrict__ out) {
    extern __shared__ float smem[];
    float* sx = smem;                          // transposed input tile
    u64* swt2 = (u64*)(smem + TILE_FLOATS);    // 343 duplicated weight pairs

    const int c   = blockIdx.y;
    const int h0  = blockIdx.x * 4;
    const int tid = threadIdx.x;

    const float* __restrict__ xc = x + (size_t)c * VOL;

    // load folded weights, duplicated into (w,w) 64-bit pairs
    for (int i = tid; i < 343; i += 256) {
        u32 wb = __float_as_uint(g_wcomb[c * WSTRIDE + i]);
        u64 wp; PACK2(wp, wb, wb);
        swt2[i] = wp;
    }
    float bias = g_wcomb[c * WSTRIDE + 343];

    // load input tile with halo (zero outside volume), transposing d to innermost.
    // logical read order [sd][sh][sw] (w fastest -> coalesced global reads)
    for (int i = tid; i < SM_D * SM_H * SM_W; i += 256) {
        int sd = i / (SM_H * SM_W);
        int r  = i % (SM_H * SM_W);
        int sh = r / SM_W;
        int sw = r % SM_W;
        int gd = sd - 3;
        int gh = h0 + sh - 3;
        int gw = sw - 3;
        float v = 0.0f;
        if ((unsigned)gd < (unsigned)DD &&
            (unsigned)gh < (unsigned)HH &&
            (unsigned)gw < (unsigned)WW)
            v = xc[(gd * HH + gh) * WW + gw];
        sx[(sh * SM_W + sw) * SDP + sd] = v;
    }
    __syncthreads();

    const int w  = tid & 63;   // 0..63
    const int hl = tid >> 6;   // 0..3

    u64 acc[8];
    {
        u32 bb = __float_as_uint(bias);
        u64 b2; PACK2(b2, bb, bb);
#pragma unroll
        for (int j = 0; j < 8; ++j) acc[j] = b2;
    }

#pragma unroll 1
    for (int dh = 0; dh < 7; ++dh) {
        const float* rowbase = sx + ((hl + dh) * SM_W + w) * SDP;
#pragma unroll
        for (int dw = 0; dw < 7; ++dw) {
            const u64* col = (const u64*)(rowbase + dw * SDP);
            // 11 aligned pairs (z0,z1)(z2,z3)...(z20,z21) via LDS.64
            u64 zp[11];
#pragma unroll
            for (int m = 0; m < 11; ++m) zp[m] = col[m];
            // 10 odd-shift pairs (z1,z2)(z3,z4)...(z19,z20)
            u64 zq[10];
#pragma unroll
            for (int m = 0; m < 10; ++m) {
                u32 lo0, hi0, lo1, hi1;
                UNPACK2(lo0, hi0, zp[m]);
                UNPACK2(lo1, hi1, zp[m + 1]);
                (void)lo0; (void)hi1;
                PACK2(zq[m], hi0, lo1);
            }
#pragma unroll
            for (int dd = 0; dd < 7; ++dd) {
                const u64 w2 = swt2[(dd * 7 + dh) * 7 + dw];
                if ((dd & 1) == 0) {
                    const int s = dd >> 1;
#pragma unroll
                    for (int j = 0; j < 8; ++j)
                        FMA2(acc[j], zp[j + s], w2, acc[j]);
                } else {
                    const int s = dd >> 1;
#pragma unroll
                    for (int j = 0; j < 8; ++j)
                        FMA2(acc[j], zq[j + s], w2, acc[j]);
                }
            }
        }
    }

    // out[c][(h*64+w)*16 + d] : 16 contiguous floats per thread
    float4* op = (float4*)(out + (size_t)c * VOL + ((size_t)(h0 + hl) * WW + w) * 16);
#pragma unroll
    for (int q = 0; q < 4; ++q) {
        u32 l0, h0_, l1, h1_;
        UNPACK2(l0, h0_, acc[2 * q]);
        UNPACK2(l1, h1_, acc[2 * q + 1]);
        op[q] = make_float4(__uint_as_float(l0), __uint_as_float(h0_),
                            __uint_as_float(l1), __uint_as_float(h1_));
    }
}

// -------------------- launch --------------------
extern "C" void kernel_launch(void* const* d_in, const int* in_sizes, int n_in,
                              void* d_out, int out_size) {
    const float* x  = (const float*)d_in[0];
    const float* w7 = (const float*)d_in[1];
    const float* b7 = (const float*)d_in[2];
    const float* w5 = (const float*)d_in[3];
    const float* b5 = (const float*)d_in[4];
    const float* w3 = (const float*)d_in[5];
    const float* b3 = (const float*)d_in[6];
    float* out = (float*)d_out;

    fold_weights_kernel<<<NCH, 256>>>(w7, b7, w5, b5, w3, b3);

    static bool attr_set = false;
    if (!attr_set) {
        cudaFuncSetAttribute(ppeg_conv_kernel,
                             cudaFuncAttributeMaxDynamicSharedMemorySize, SMEM_BYTES);
        attr_set = true;
    }

    dim3 grid(HH / 4, NCH);   // 16 h-tiles x 512 channels
    ppeg_conv_kernel<<<grid, 256, SMEM_BYTES>>>(x, out);
}

// round 3
// speedup vs baseline: 1.5789x; 1.5789x over previous
#include <cuda_runtime.h>
#include <cuda_bf16.h>
#include <cstdint>

// ---------------------------------------------------------------------------
// PPEG: out = dwconv7(x) + x + dwconv5(x) + dwconv3(x)  (depthwise, per-channel)
// Folded into ONE 7x7x7 depthwise conv per channel + combined bias.
//
// x layout  (per channel c): volume[d][h][w], d=16, h=64, w=64 (w contiguous)
// out layout(per channel c): [h][w][d] with d contiguous (stride-1)
// ---------------------------------------------------------------------------

#define NCH   512
#define DD    16
#define HH    64
#define WW    64
#define VOL   (DD*HH*WW)      // 65536 per channel

#define WSTRIDE 352           // per-channel slot in g_wcomb (343 taps + bias)
__device__ float g_wcomb[NCH * WSTRIDE];

// -------------------- weight folding --------------------
__global__ void fold_weights_kernel(const float* __restrict__ w7,
                                    const float* __restrict__ b7,
                                    const float* __restrict__ w5,
                                    const float* __restrict__ b5,
                                    const float* __restrict__ w3,
                                    const float* __restrict__ b3) {
    int c = blockIdx.x;
    for (int t = threadIdx.x; t < 343; t += blockDim.x) {
        int dd = t / 49;
        int r  = t % 49;
        int dh = r / 7;
        int dw = r % 7;
        float v = w7[c * 343 + t];
        if (dd >= 1 && dd <= 5 && dh >= 1 && dh <= 5 && dw >= 1 && dw <= 5)
            v += w5[c * 125 + (dd - 1) * 25 + (dh - 1) * 5 + (dw - 1)];
        if (dd >= 2 && dd <= 4 && dh >= 2 && dh <= 4 && dw >= 2 && dw <= 4)
            v += w3[c * 27 + (dd - 2) * 9 + (dh - 2) * 3 + (dw - 2)];
        if (t == 171) v += 1.0f;   // identity: center tap (3,3,3)
        g_wcomb[c * WSTRIDE + t] = v;
    }
    if (threadIdx.x == 0)
        g_wcomb[c * WSTRIDE + 343] = b7[c] + b5[c] + b3[c];
}

// -------------------- main conv --------------------
// CTA: one channel, 4 consecutive h rows, full W, full D.
// Thread: one (h,w) -> 16 d-outputs.
// Smem tile d-innermost: [sh=10][sw=70][sd_pad=26], halo 3 each side, zero-padded.
// Column stride 26 words: the two 16-lane LDS.64 phases cover all 32 banks
// (gcd(26,32)=2 -> 16 distinct even banks lo-word, 16 odd banks hi-word).
#define SM_D  22
#define SDP   26
#define SM_H  10
#define SM_W  70
#define NCOLS (SM_H * SM_W)                  // 700 (sh,sw) columns
#define TILE_FLOATS (NCOLS * SDP)            // 18200
#define SMEM_BYTES  (TILE_FLOATS * 4 + 344 * 4)

__global__ __launch_bounds__(256, 3)
void ppeg_conv_kernel(const float* __restrict__ x, float* __restrict__ out) {
    extern __shared__ float smem[];
    float* sx  = smem;                 // transposed input tile
    float* swt = smem + TILE_FLOATS;   // 343 folded weights + bias

    const int c   = blockIdx.y;
    const int h0  = blockIdx.x * 4;
    const int tid = threadIdx.x;

    const float* __restrict__ xc = x + (size_t)c * VOL;

    // folded weights for this channel
    for (int i = tid; i < 344; i += 256)
        swt[i] = g_wcomb[c * WSTRIDE + i];

    // ---- tile load: one (sh,sw) column of 22 d-values per iteration ----
    // gd = sd-3: sd<3 or sd>18 are compile-time zeros (only 16 runtime loads).
    for (int col = tid; col < NCOLS; col += 256) {
        int sh = col / SM_W;           // mul-shift, cheap
        int sw = col - sh * SM_W;
        int gh = h0 + sh - 3;
        int gw = sw - 3;
        bool okhw = ((unsigned)gh < (unsigned)HH) && ((unsigned)gw < (unsigned)WW);
        const float* gp = xc + (gh * WW + gw);

        float z[SM_D];
#pragma unroll
        for (int sd = 0; sd < SM_D; ++sd) {
            int gd = sd - 3;
            float v = 0.0f;
            if (gd >= 0 && gd < DD)            // compile-time
                v = okhw ? __ldg(gp + gd * (HH * WW)) : 0.0f;
            z[sd] = v;
        }

        float2* sp = (float2*)(sx + col * SDP);   // 8B aligned (26*4=104 % 8 == 0)
#pragma unroll
        for (int m = 0; m < 11; ++m)
            sp[m] = make_float2(z[2 * m], z[2 * m + 1]);
    }
    __syncthreads();

    const int w  = tid & 63;   // 0..63
    const int hl = tid >> 6;   // 0..3

    const float bias = swt[343];
    float acc[16];
#pragma unroll
    for (int o = 0; o < 16; ++o) acc[o] = bias;

#pragma unroll 1
    for (int dh = 0; dh < 7; ++dh) {
        const float* rowbase = sx + ((hl + dh) * SM_W + w) * SDP;
        const float* wrow    = swt + dh * 7;
#pragma unroll
        for (int dw = 0; dw < 7; ++dw) {
            // 22-deep d-column as 11 LDS.64
            float2 zv[11];
            const float2* col2 = (const float2*)(rowbase + dw * SDP);
#pragma unroll
            for (int m = 0; m < 11; ++m) zv[m] = col2[m];
            float z[SM_D];
#pragma unroll
            for (int m = 0; m < 11; ++m) { z[2*m] = zv[m].x; z[2*m+1] = zv[m].y; }
#pragma unroll
            for (int dd = 0; dd < 7; ++dd) {
                const float wv = wrow[dd * 49 + dw];
#pragma unroll
                for (int o = 0; o < 16; ++o)
                    acc[o] = fmaf(z[o + dd], wv, acc[o]);
            }
        }
    }

    // out[c][(h*64+w)*16 + d] : 16 contiguous floats per thread
    float4* op = (float4*)(out + (size_t)c * VOL + ((size_t)(h0 + hl) * WW + w) * 16);
    op[0] = make_float4(acc[0],  acc[1],  acc[2],  acc[3]);
    op[1] = make_float4(acc[4],  acc[5],  acc[6],  acc[7]);
    op[2] = make_float4(acc[8],  acc[9],  acc[10], acc[11]);
    op[3] = make_float4(acc[12], acc[13], acc[14], acc[15]);
}

// -------------------- launch --------------------
extern "C" void kernel_launch(void* const* d_in, const int* in_sizes, int n_in,
                              void* d_out, int out_size) {
    const float* x  = (const float*)d_in[0];
    const float* w7 = (const float*)d_in[1];
    const float* b7 = (const float*)d_in[2];
    const float* w5 = (const float*)d_in[3];
    const float* b5 = (const float*)d_in[4];
    const float* w3 = (const float*)d_in[5];
    const float* b3 = (const float*)d_in[6];
    float* out = (float*)d_out;

    fold_weights_kernel<<<NCH, 256>>>(w7, b7, w5, b5, w3, b3);

    static bool attr_set = false;
    if (!attr_set) {
        cudaFuncSetAttribute(ppeg_conv_kernel,
                             cudaFuncAttributeMaxDynamicSharedMemorySize, SMEM_BYTES);
        attr_set = true;
    }

    dim3 grid(HH / 4, NCH);   // 16 h-tiles x 512 channels
    ppeg_conv_kernel<<<grid, 256, SMEM_BYTES>>>(x, out);
}

// round 4
// speedup vs baseline: 1.6316x; 1.0333x over previous
#include <cuda_runtime.h>
#include <cuda_bf16.h>
#include <cstdint>

// ---------------------------------------------------------------------------
// PPEG: out = dwconv7(x) + x + dwconv5(x) + dwconv3(x)  (depthwise, per-channel)
// Folded into ONE 7x7x7 depthwise conv per channel + combined bias.
// Even-dd taps use packed fma.rn.f32x2 on aligned float2 pairs (no repack movs);
// odd-dd taps use scalar FFMA into a separate accumulator bank.
//
// x layout  (per channel c): volume[d][h][w], d=16, h=64, w=64 (w contiguous)
// out layout(per channel c): [h][w][d] with d contiguous (stride-1)
// ---------------------------------------------------------------------------

#define NCH   512
#define DD    16
#define HH    64
#define WW    64
#define VOL   (DD*HH*WW)      // 65536 per channel

#define WSTRIDE 352           // per-channel slot in g_wcomb (343 taps + bias)
__device__ float g_wcomb[NCH * WSTRIDE];

typedef unsigned long long u64;
typedef unsigned int u32;

// packed FMA building the a-operand from two scalar float regs (ptxas aliases
// the pair when they already live in an even/odd pair from LDS.64)
#define FMA2P(acc_, alo_, ahi_, w2_) \
    asm("{\n\t.reg .b64 _a;\n\tmov.b64 _a, {%1, %2};\n\t" \
        "fma.rn.f32x2 %0, _a, %3, %0;\n\t}" \
        : "+l"(acc_) : "f"(alo_), "f"(ahi_), "l"(w2_))

// -------------------- weight folding --------------------
__global__ void fold_weights_kernel(const float* __restrict__ w7,
                                    const float* __restrict__ b7,
                                    const float* __restrict__ w5,
                                    const float* __restrict__ b5,
                                    const float* __restrict__ w3,
                                    const float* __restrict__ b3) {
    int c = blockIdx.x;
    for (int t = threadIdx.x; t < 343; t += blockDim.x) {
        int dd = t / 49;
        int r  = t % 49;
        int dh = r / 7;
        int dw = r % 7;
        float v = w7[c * 343 + t];
        if (dd >= 1 && dd <= 5 && dh >= 1 && dh <= 5 && dw >= 1 && dw <= 5)
            v += w5[c * 125 + (dd - 1) * 25 + (dh - 1) * 5 + (dw - 1)];
        if (dd >= 2 && dd <= 4 && dh >= 2 && dh <= 4 && dw >= 2 && dw <= 4)
            v += w3[c * 27 + (dd - 2) * 9 + (dh - 2) * 3 + (dw - 2)];
        if (t == 171) v += 1.0f;   // identity: center tap (3,3,3)
        g_wcomb[c * WSTRIDE + t] = v;
    }
    if (threadIdx.x == 0)
        g_wcomb[c * WSTRIDE + 343] = b7[c] + b5[c] + b3[c];
}

// -------------------- main conv --------------------
// CTA: one channel, 4 consecutive h rows, full W, full D.
// Thread: one (h,w) -> 16 d-outputs.
// Smem tile d-innermost: [sh=10][sw=70][sd_pad=26], halo 3 each side, zero-padded.
#define SM_D  22
#define SDP   26
#define SM_H  10
#define SM_W  70
#define NCOLS (SM_H * SM_W)                  // 700 (sh,sw) columns
#define TILE_FLOATS (NCOLS * SDP)            // 18200
#define SMEM_BYTES  (TILE_FLOATS * 4 + 343 * 8 + 8)

__global__ __launch_bounds__(256, 3)
void ppeg_conv_kernel(const float* __restrict__ x, float* __restrict__ out) {
    extern __shared__ float smem[];
    float* sx  = smem;                        // transposed input tile
    u64*  swt2 = (u64*)(smem + TILE_FLOATS);  // 343 duplicated (w,w) weight pairs
    float* sbias = (float*)(swt2 + 343);

    const int c   = blockIdx.y;
    const int h0  = blockIdx.x * 4;
    const int tid = threadIdx.x;

    const float* __restrict__ xc = x + (size_t)c * VOL;

    // folded weights for this channel, duplicated into (w,w) pairs
    for (int i = tid; i < 343; i += 256) {
        float wv = g_wcomb[c * WSTRIDE + i];
        ((float2*)swt2)[i] = make_float2(wv, wv);
    }
    if (tid == 0) sbias[0] = g_wcomb[c * WSTRIDE + 343];

    // ---- tile load: one (sh,sw) column of 22 d-values per iteration ----
    for (int col = tid; col < NCOLS; col += 256) {
        int sh = col / SM_W;
        int sw = col - sh * SM_W;
        int gh = h0 + sh - 3;
        int gw = sw - 3;
        bool okhw = ((unsigned)gh < (unsigned)HH) && ((unsigned)gw < (unsigned)WW);
        const float* gp = xc + (gh * WW + gw);

        float z[SM_D];
#pragma unroll
        for (int sd = 0; sd < SM_D; ++sd) {
            int gd = sd - 3;
            float v = 0.0f;
            if (gd >= 0 && gd < DD)            // compile-time predicate
                v = okhw ? __ldg(gp + gd * (HH * WW)) : 0.0f;
            z[sd] = v;
        }

        float2* sp = (float2*)(sx + col * SDP);   // 8B aligned (26*4 % 8 == 0)
#pragma unroll
        for (int m = 0; m < 11; ++m)
            sp[m] = make_float2(z[2 * m], z[2 * m + 1]);
    }
    __syncthreads();

    const int w  = tid & 63;   // 0..63
    const int hl = tid >> 6;   // 0..3

    const float bias = sbias[0];
    u64   accE[8];             // even-dd taps, packed f32x2
    float accO[16];            // odd-dd taps + bias, scalar
#pragma unroll
    for (int j = 0; j < 8; ++j) accE[j] = 0ull;
#pragma unroll
    for (int o = 0; o < 16; ++o) accO[o] = bias;

#pragma unroll 1
    for (int dh = 0; dh < 7; ++dh) {
        const float* rowbase = sx + ((hl + dh) * SM_W + w) * SDP;
        const u64*   wrow    = swt2 + dh * 7;
#pragma unroll
        for (int dw = 0; dw < 7; ++dw) {
            // 22-deep d-column as 11 LDS.64 -> register pairs
            float2 zv[11];
            const float2* col2 = (const float2*)(rowbase + dw * SDP);
#pragma unroll
            for (int m = 0; m < 11; ++m) zv[m] = col2[m];

            // even dd: packed FMA on aligned pairs
#pragma unroll
            for (int s = 0; s < 4; ++s) {            // dd = 2s
                const u64 w2 = wrow[(2 * s) * 49 + dw];
#pragma unroll
                for (int j = 0; j < 8; ++j)
                    FMA2P(accE[j], zv[j + s].x, zv[j + s].y, w2);
            }
            // odd dd: scalar FMA
#pragma unroll
            for (int s = 0; s < 3; ++s) {            // dd = 2s+1
                const float wv = ((const float*)&wrow[(2 * s + 1) * 49 + dw])[0];
#pragma unroll
                for (int o = 0; o < 16; ++o) {
                    const int k = o + 2 * s + 1;
                    const float zk = (k & 1) ? zv[k >> 1].y : zv[k >> 1].x;
                    accO[o] = fmaf(zk, wv, accO[o]);
                }
            }
        }
    }

    // merge banks and store: out[c][(h*64+w)*16 + d], 16 contiguous floats
    float res[16];
#pragma unroll
    for (int j = 0; j < 8; ++j) {
        float lo, hi;
        asm("mov.b64 {%0, %1}, %2;" : "=f"(lo), "=f"(hi) : "l"(accE[j]));
        res[2 * j]     = accO[2 * j]     + lo;
        res[2 * j + 1] = accO[2 * j + 1] + hi;
    }

    float4* op = (float4*)(out + (size_t)c * VOL + ((size_t)(h0 + hl) * WW + w) * 16);
    op[0] = make_float4(res[0],  res[1],  res[2],  res[3]);
    op[1] = make_float4(res[4],  res[5],  res[6],  res[7]);
    op[2] = make_float4(res[8],  res[9],  res[10], res[11]);
    op[3] = make_float4(res[12], res[13], res[14], res[15]);
}

// -------------------- launch --------------------
extern "C" void kernel_launch(void* const* d_in, const int* in_sizes, int n_in,
                              void* d_out, int out_size) {
    const float* x  = (const float*)d_in[0];
    const float* w7 = (const float*)d_in[1];
    const float* b7 = (const float*)d_in[2];
    const float* w5 = (const float*)d_in[3];
    const float* b5 = (const float*)d_in[4];
    const float* w3 = (const float*)d_in[5];
    const float* b3 = (const float*)d_in[6];
    float* out = (float*)d_out;

    fold_weights_kernel<<<NCH, 256>>>(w7, b7, w5, b5, w3, b3);

    static bool attr_set = false;
    if (!attr_set) {
        cudaFuncSetAttribute(ppeg_conv_kernel,
                             cudaFuncAttributeMaxDynamicSharedMemorySize, SMEM_BYTES);
        attr_set = true;
    }

    dim3 grid(HH / 4, NCH);   // 16 h-tiles x 512 channels
    ppeg_conv_kernel<<<grid, 256, SMEM_BYTES>>>(x, out);
}